// round 1
// baseline (speedup 1.0000x reference)
#include <cuda_runtime.h>

// SparseDenseMatMul: out[m, n] = sum_{i: rows[i]==m} vals[i] * A[cols[i], n]
// M = 100000, K = 100000, N = 64, NNZ = 1.6M
//
// Inputs (metadata order):
//   d_in[0] = vals  (float,  NNZ)
//   d_in[1] = A     (float,  K*N)
//   d_in[2] = rows  (int,    NNZ)
//   d_in[3] = cols  (int,    NNZ)
// Output: float, M*N
//
// Strategy: zero-fill out, then 16 threads per nnz, each owning one float4
// slice of the 64-wide row. Gather A[col] (float4), scale by val, and
// scatter with red.global.add.v4.f32 (vector reduction, no return).

#define N_COLS 64
#define QUADS_PER_ROW (N_COLS / 4)   // 16

__global__ void zero_out_kernel(float4* __restrict__ out4, int n4) {
    int i = blockIdx.x * blockDim.x + threadIdx.x;
    if (i < n4) out4[i] = make_float4(0.f, 0.f, 0.f, 0.f);
}

__global__ void __launch_bounds__(256)
spmm_coo_kernel(const float* __restrict__ vals,
                const float4* __restrict__ A4,
                const int* __restrict__ rows,
                const int* __restrict__ cols,
                float* __restrict__ out,
                int nnz) {
    long long gt = (long long)blockIdx.x * blockDim.x + threadIdx.x;
    int i   = (int)(gt >> 4);       // nnz index
    int sub = (int)(gt & 15);       // which float4 of the 64-wide row
    if (i >= nnz) return;

    int   r = rows[i];
    int   c = cols[i];
    float v = vals[i];

    float4 a = A4[(long long)c * QUADS_PER_ROW + sub];
    float4 p;
    p.x = a.x * v;
    p.y = a.y * v;
    p.z = a.z * v;
    p.w = a.w * v;

    float* dst = out + (long long)r * N_COLS + sub * 4;
    asm volatile("red.global.add.v4.f32 [%0], {%1, %2, %3, %4};"
                 :: "l"(dst), "f"(p.x), "f"(p.y), "f"(p.z), "f"(p.w)
                 : "memory");
}

extern "C" void kernel_launch(void* const* d_in, const int* in_sizes, int n_in,
                              void* d_out, int out_size) {
    const float* vals = (const float*)d_in[0];
    const float* A    = (const float*)d_in[1];
    const int*   rows = (const int*)d_in[2];
    const int*   cols = (const int*)d_in[3];
    float*       out  = (float*)d_out;

    int nnz = in_sizes[0];

    // 1) zero the output (poisoned by harness)
    int n4 = out_size / 4;
    {
        int threads = 256;
        int blocks  = (n4 + threads - 1) / threads;
        zero_out_kernel<<<blocks, threads>>>((float4*)out, n4);
    }

    // 2) scatter-add contributions
    {
        long long total_threads = (long long)nnz * QUADS_PER_ROW;
        int threads = 256;
        long long blocks = (total_threads + threads - 1) / threads;
        spmm_coo_kernel<<<(int)blocks, threads>>>(vals, (const float4*)A,
                                                  rows, cols, out, nnz);
    }
}

// round 4
// speedup vs baseline: 1.1646x; 1.1646x over previous
#include <cuda_runtime.h>

// SparseDenseMatMul: out[m,n] = sum_{i: rows[i]==m} vals[i] * A[cols[i], n]
// M = 100000, K = 100000, N = 64, NNZ = 1.6M
//
// Inputs (metadata order):
//   d_in[0] = vals (float, NNZ), d_in[1] = A (float, K*N),
//   d_in[2] = rows (int, NNZ),   d_in[3] = cols (int, NNZ)
// Output: float, M*N
//
// Strategy: bin nnz into fixed-capacity per-row buckets (Phase B, scalar
// atomics only), then gather-compute each output row with one warp and a
// single plain store (Phase C, atomic-free). Overflow (>64 nnz in a row,
// probability ~0 for Poisson(16)) handled by a spill list (Phase D).

#define N_COLS     64
#define M_ROWS     100000
#define BUCKET_CAP 64
#define OVF_CAP    8192

__device__ int  d_cnt[M_ROWS];
__device__ int2 d_bucket[(size_t)M_ROWS * BUCKET_CAP];   // (col, val-bits)
__device__ int  d_ovf_cnt;
__device__ int  d_ovf[OVF_CAP];

// ---------------- Phase A: zero counters ----------------
__global__ void phaseA_zero(int m) {
    int i = blockIdx.x * blockDim.x + threadIdx.x;
    if (i < m) d_cnt[i] = 0;
    if (i == 0) d_ovf_cnt = 0;
}

// ---------------- Phase B: bin nnz into per-row buckets ----------------
__global__ void __launch_bounds__(256)
phaseB_scatter(const float* __restrict__ vals,
               const int*   __restrict__ rows,
               const int*   __restrict__ cols,
               int nnz) {
    int i = blockIdx.x * blockDim.x + threadIdx.x;
    if (i >= nnz) return;
    // Issue all three loads up front so they overlap the atomic's latency.
    int   r = rows[i];
    int   c = cols[i];
    float v = vals[i];
    int pos = atomicAdd(&d_cnt[r], 1);
    if (pos < BUCKET_CAP) {
        d_bucket[(size_t)r * BUCKET_CAP + pos] = make_int2(c, __float_as_int(v));
    } else {
        int o = atomicAdd(&d_ovf_cnt, 1);
        if (o < OVF_CAP) d_ovf[o] = i;
    }
}

// ---------------- Phase C: warp-per-row gather SpMM (no atomics) -------
__global__ void __launch_bounds__(256)
phaseC_spmm(const float2* __restrict__ A2,
            float2*       __restrict__ out2,
            int m) {
    int gtid = blockIdx.x * blockDim.x + threadIdx.x;
    int w    = gtid >> 5;          // one warp per output row
    int lane = threadIdx.x & 31;
    if (w >= m) return;

    int c = __ldg(&d_cnt[w]);
    if (c > BUCKET_CAP) c = BUCKET_CAP;

    const int2* bk = d_bucket + (size_t)w * BUCKET_CAP;

    // Coalesced preload of this row's bucket entries into lane registers.
    int2 e0 = make_int2(0, 0), e1 = make_int2(0, 0);
    if (lane < c)      e0 = __ldg(&bk[lane]);
    if (lane + 32 < c) e1 = __ldg(&bk[lane + 32]);

    float accx = 0.f, accy = 0.f;   // lane owns out columns 2*lane, 2*lane+1

    int c0 = c < 32 ? c : 32;
    for (int k = 0; k < c0; k++) {
        int   col = __shfl_sync(0xffffffffu, e0.x, k);
        float v   = __int_as_float(__shfl_sync(0xffffffffu, e0.y, k));
        float2 a  = __ldg(&A2[(size_t)col * (N_COLS / 2) + lane]);
        accx = fmaf(v, a.x, accx);
        accy = fmaf(v, a.y, accy);
    }
    for (int k = 32; k < c; k++) {
        int   col = __shfl_sync(0xffffffffu, e1.x, k - 32);
        float v   = __int_as_float(__shfl_sync(0xffffffffu, e1.y, k - 32));
        float2 a  = __ldg(&A2[(size_t)col * (N_COLS / 2) + lane]);
        accx = fmaf(v, a.x, accx);
        accy = fmaf(v, a.y, accy);
    }

    out2[(size_t)w * (N_COLS / 2) + lane] = make_float2(accx, accy);
}

// ---------------- Phase D: apply spill entries (expected: none) --------
__global__ void phaseD_overflow(const float* __restrict__ vals,
                                const float* __restrict__ A,
                                const int*   __restrict__ rows,
                                const int*   __restrict__ cols,
                                float*       __restrict__ out) {
    int n = d_ovf_cnt;
    if (n > OVF_CAP) n = OVF_CAP;
    // 16 work items (one float4 slice) per spilled nnz
    for (int j = threadIdx.x; j < n * 16; j += blockDim.x) {
        int i   = d_ovf[j >> 4];
        int sub = j & 15;
        int r = rows[i];
        int c = cols[i];
        float v = vals[i];
        const float4* a4 = (const float4*)(A + (size_t)c * N_COLS);
        float4 a = a4[sub];
        float* dst = out + (size_t)r * N_COLS + sub * 4;
        asm volatile("red.global.add.v4.f32 [%0], {%1, %2, %3, %4};"
                     :: "l"(dst), "f"(a.x * v), "f"(a.y * v),
                        "f"(a.z * v), "f"(a.w * v)
                     : "memory");
    }
}

extern "C" void kernel_launch(void* const* d_in, const int* in_sizes, int n_in,
                              void* d_out, int out_size) {
    const float* vals = (const float*)d_in[0];
    const float* A    = (const float*)d_in[1];
    const int*   rows = (const int*)d_in[2];
    const int*   cols = (const int*)d_in[3];
    float*       out  = (float*)d_out;

    int nnz = in_sizes[0];
    int m   = out_size / N_COLS;
    if (m > M_ROWS) m = M_ROWS;   // scratch capacity bound (shapes are fixed)

    // Phase A: zero counters
    {
        int threads = 256;
        int blocks  = (m + threads - 1) / threads;
        phaseA_zero<<<blocks, threads>>>(m);
    }
    // Phase B: bin into buckets
    {
        int threads = 256;
        int blocks  = (nnz + threads - 1) / threads;
        phaseB_scatter<<<blocks, threads>>>(vals, rows, cols, nnz);
    }
    // Phase C: warp-per-row gather SpMM (also writes zeros for empty rows)
    {
        int threads = 256;                       // 8 warps / block
        int blocks  = (m * 32 + threads - 1) / threads;
        phaseC_spmm<<<blocks, threads>>>((const float2*)A, (float2*)out, m);
    }
    // Phase D: spill entries via vector RED (after C's plain stores)
    phaseD_overflow<<<1, 256>>>(vals, A, rows, cols, out);
}